// round 3
// baseline (speedup 1.0000x reference)
#include <cuda_runtime.h>
#include <math.h>

// Problem constants
constexpr int B_  = 4;
constexpr int S_  = 2048;
constexpr int D_  = 1024;
constexpr int H_  = 16;
constexpr int HD_ = 64;
constexpr int M_  = B_ * S_;   // 8192

// Scratch (static device arrays — allocation-free per harness rules)
__device__ float g_Q[(size_t)M_ * D_];
__device__ float g_K[(size_t)M_ * D_];
__device__ float g_V[(size_t)M_ * D_];
__device__ float g_A[(size_t)M_ * D_];

// ---------------------------------------------------------------------------
// SGEMM: C[M,1024] = A[M,1024] @ W[1024,1024] (+ bias)
// 128x128 block tile, BK=16, 256 threads, 8x8 microtile, float4 everywhere.
// ---------------------------------------------------------------------------
__global__ __launch_bounds__(256, 2)
void sgemm128(const float* __restrict__ A, const float* __restrict__ W,
              const float* __restrict__ bias, float* __restrict__ C) {
    constexpr int Kd = 1024, Nd = 1024;
    __shared__ float As[16][128];   // transposed A tile: As[k][m]
    __shared__ float Bs[16][128];   // Bs[k][n]

    const int tid = threadIdx.x;
    const int tx = tid & 15, ty = tid >> 4;
    const int row0 = blockIdx.y * 128;
    const int col0 = blockIdx.x * 128;

    float acc[8][8];
#pragma unroll
    for (int i = 0; i < 8; i++)
#pragma unroll
        for (int j = 0; j < 8; j++) acc[i][j] = 0.f;

    const int arow = tid >> 2;          // 0..63
    const int acol = (tid & 3) << 2;    // 0,4,8,12
    const int brow = tid >> 5;          // 0..7
    const int bcol = (tid & 31) << 2;   // 0..124

    for (int k0 = 0; k0 < Kd; k0 += 16) {
#pragma unroll
        for (int u = 0; u < 2; u++) {
            int r = arow + u * 64;
            float4 v = *reinterpret_cast<const float4*>(
                A + (size_t)(row0 + r) * Kd + k0 + acol);
            As[acol + 0][r] = v.x;
            As[acol + 1][r] = v.y;
            As[acol + 2][r] = v.z;
            As[acol + 3][r] = v.w;
        }
#pragma unroll
        for (int u = 0; u < 2; u++) {
            int r = brow + u * 8;
            *reinterpret_cast<float4*>(&Bs[r][bcol]) =
                *reinterpret_cast<const float4*>(
                    W + (size_t)(k0 + r) * Nd + col0 + bcol);
        }
        __syncthreads();

#pragma unroll
        for (int kk = 0; kk < 16; kk++) {
            float a[8], b[8];
            *reinterpret_cast<float4*>(a)     = *reinterpret_cast<float4*>(&As[kk][ty * 8]);
            *reinterpret_cast<float4*>(a + 4) = *reinterpret_cast<float4*>(&As[kk][ty * 8 + 4]);
            *reinterpret_cast<float4*>(b)     = *reinterpret_cast<float4*>(&Bs[kk][tx * 8]);
            *reinterpret_cast<float4*>(b + 4) = *reinterpret_cast<float4*>(&Bs[kk][tx * 8 + 4]);
#pragma unroll
            for (int i = 0; i < 8; i++)
#pragma unroll
                for (int j = 0; j < 8; j++)
                    acc[i][j] = fmaf(a[i], b[j], acc[i][j]);
        }
        __syncthreads();
    }

#pragma unroll
    for (int i = 0; i < 8; i++) {
        int r = row0 + ty * 8 + i;
#pragma unroll
        for (int j = 0; j < 8; j += 4) {
            int c = col0 + tx * 8 + j;
            float4 v;
            v.x = acc[i][j];     v.y = acc[i][j + 1];
            v.z = acc[i][j + 2]; v.w = acc[i][j + 3];
            if (bias) {
                v.x += bias[c];     v.y += bias[c + 1];
                v.z += bias[c + 2]; v.w += bias[c + 3];
            }
            *reinterpret_cast<float4*>(C + (size_t)r * Nd + c) = v;
        }
    }
}

// ---------------------------------------------------------------------------
// Flash attention v2, fp32.
// Block = 64 query rows of one (b,h); key tile 64; 256 threads (16x16).
// 4x4 microtiles, all smem traffic LDS.128 (pitch 68 floats, float4-aligned,
// conflict-free per quarter-warp phase). Softmax fully in registers with
// half-warp shfl reductions (each row owned by 16 lanes of one half-warp).
// Dynamic smem: 4 tiles of 64x68 + 2x64 row stats = ~70KB.
// ---------------------------------------------------------------------------
constexpr int PIT2 = 68;
constexpr int FA_SMEM = (4 * 64 * PIT2 + 128) * (int)sizeof(float);

__global__ __launch_bounds__(256)
void flash_attn2(const float* __restrict__ Qg, const float* __restrict__ Kg,
                 const float* __restrict__ Vg, float* __restrict__ Og) {
    extern __shared__ float smf[];
    float* Qs = smf;                    // 64 x PIT2
    float* Ks = Qs + 64 * PIT2;
    float* Vs = Ks + 64 * PIT2;
    float* Ps = Vs + 64 * PIT2;
    float* mrow = Ps + 64 * PIT2;       // 64
    float* lrow = mrow + 64;            // 64

    const int tid = threadIdx.x;
    const int tx = tid & 15, ty = tid >> 4;
    const int b = blockIdx.y >> 4;      // H_ = 16
    const int h = blockIdx.y & 15;
    const int q0 = blockIdx.x * 64;
    const size_t hbase = (size_t)b * S_ * D_ + (size_t)h * HD_;

    // Load Q tile 64x64 (float4)
#pragma unroll
    for (int u = 0; u < 4; u++) {
        int idx = tid + u * 256;
        int r = idx >> 4;
        int c = (idx & 15) << 2;
        float4 v = *reinterpret_cast<const float4*>(
            Qg + hbase + (size_t)(q0 + r) * D_ + c);
        *reinterpret_cast<float4*>(&Qs[r * PIT2 + c]) = v;
    }
    if (tid < 64) { mrow[tid] = -INFINITY; lrow[tid] = 0.f; }

    float o[4][4];
#pragma unroll
    for (int i = 0; i < 4; i++)
#pragma unroll
        for (int j = 0; j < 4; j++) o[i][j] = 0.f;

    const int r4 = ty * 4;   // query-row group (0..60)
    const int c4 = tx * 4;   // key-col / headdim-col group (0..60)
    const float scale = 0.03125f;  // 1/sqrt(1024)

    for (int k0 = 0; k0 < S_; k0 += 64) {
        __syncthreads();   // previous PV reads of Ks/Vs/Ps done; Q load visible
        // Load K,V tiles 64x64 (float4)
#pragma unroll
        for (int u = 0; u < 4; u++) {
            int idx = tid + u * 256;
            int r = idx >> 4;
            int c = (idx & 15) << 2;
            float4 kv = *reinterpret_cast<const float4*>(
                Kg + hbase + (size_t)(k0 + r) * D_ + c);
            float4 vv = *reinterpret_cast<const float4*>(
                Vg + hbase + (size_t)(k0 + r) * D_ + c);
            *reinterpret_cast<float4*>(&Ks[r * PIT2 + c]) = kv;
            *reinterpret_cast<float4*>(&Vs[r * PIT2 + c]) = vv;
        }
        __syncthreads();

        // S = Q K^T : 4x4 per thread, float4 over d
        float s[4][4];
#pragma unroll
        for (int i = 0; i < 4; i++)
#pragma unroll
            for (int j = 0; j < 4; j++) s[i][j] = 0.f;

#pragma unroll
        for (int d = 0; d < 64; d += 4) {
            float4 qa[4], kb[4];
#pragma unroll
            for (int i = 0; i < 4; i++)
                qa[i] = *reinterpret_cast<float4*>(&Qs[(r4 + i) * PIT2 + d]);
#pragma unroll
            for (int j = 0; j < 4; j++)
                kb[j] = *reinterpret_cast<float4*>(&Ks[(c4 + j) * PIT2 + d]);
#pragma unroll
            for (int i = 0; i < 4; i++)
#pragma unroll
                for (int j = 0; j < 4; j++) {
                    s[i][j] = fmaf(qa[i].x, kb[j].x, s[i][j]);
                    s[i][j] = fmaf(qa[i].y, kb[j].y, s[i][j]);
                    s[i][j] = fmaf(qa[i].z, kb[j].z, s[i][j]);
                    s[i][j] = fmaf(qa[i].w, kb[j].w, s[i][j]);
                }
        }

        // Online softmax: rows r4..r4+3 each owned by the 16 lanes sharing ty
        // (one half-warp) -> shfl_xor width-16 reductions.
        float cr[4];
#pragma unroll
        for (int i = 0; i < 4; i++) {
            float mx = fmaxf(fmaxf(s[i][0], s[i][1]), fmaxf(s[i][2], s[i][3]));
            mx *= scale;  // scale first (monotone), then reduce
#pragma unroll
            for (int off = 8; off >= 1; off >>= 1)
                mx = fmaxf(mx, __shfl_xor_sync(0xffffffffu, mx, off, 16));
            float m_old = mrow[r4 + i];
            float m_new = fmaxf(m_old, mx);
            cr[i] = __expf(m_old - m_new);
            float e0 = __expf(fmaf(s[i][0], scale, -m_new));
            float e1 = __expf(fmaf(s[i][1], scale, -m_new));
            float e2 = __expf(fmaf(s[i][2], scale, -m_new));
            float e3 = __expf(fmaf(s[i][3], scale, -m_new));
            float rs = (e0 + e1) + (e2 + e3);
#pragma unroll
            for (int off = 8; off >= 1; off >>= 1)
                rs += __shfl_xor_sync(0xffffffffu, rs, off, 16);
            if (tx == 0) {
                mrow[r4 + i] = m_new;
                lrow[r4 + i] = lrow[r4 + i] * cr[i] + rs;
            }
            float4 e; e.x = e0; e.y = e1; e.z = e2; e.w = e3;
            *reinterpret_cast<float4*>(&Ps[(r4 + i) * PIT2 + c4]) = e;
            // rescale running output
            o[i][0] *= cr[i]; o[i][1] *= cr[i];
            o[i][2] *= cr[i]; o[i][3] *= cr[i];
        }
        __syncthreads();   // Ps complete (all tx of each row), Vs stable

        // O += P @ V : 4x4 per thread, float4 over k
#pragma unroll
        for (int k = 0; k < 64; k += 4) {
            float4 pv[4], vv[4];
#pragma unroll
            for (int i = 0; i < 4; i++)
                pv[i] = *reinterpret_cast<float4*>(&Ps[(r4 + i) * PIT2 + k]);
#pragma unroll
            for (int t = 0; t < 4; t++)
                vv[t] = *reinterpret_cast<float4*>(&Vs[(k + t) * PIT2 + c4]);
#pragma unroll
            for (int i = 0; i < 4; i++) {
                o[i][0] = fmaf(pv[i].x, vv[0].x, o[i][0]);
                o[i][1] = fmaf(pv[i].x, vv[0].y, o[i][1]);
                o[i][2] = fmaf(pv[i].x, vv[0].z, o[i][2]);
                o[i][3] = fmaf(pv[i].x, vv[0].w, o[i][3]);
                o[i][0] = fmaf(pv[i].y, vv[1].x, o[i][0]);
                o[i][1] = fmaf(pv[i].y, vv[1].y, o[i][1]);
                o[i][2] = fmaf(pv[i].y, vv[1].z, o[i][2]);
                o[i][3] = fmaf(pv[i].y, vv[1].w, o[i][3]);
                o[i][0] = fmaf(pv[i].z, vv[2].x, o[i][0]);
                o[i][1] = fmaf(pv[i].z, vv[2].y, o[i][1]);
                o[i][2] = fmaf(pv[i].z, vv[2].z, o[i][2]);
                o[i][3] = fmaf(pv[i].z, vv[2].w, o[i][3]);
                o[i][0] = fmaf(pv[i].w, vv[3].x, o[i][0]);
                o[i][1] = fmaf(pv[i].w, vv[3].y, o[i][1]);
                o[i][2] = fmaf(pv[i].w, vv[3].z, o[i][2]);
                o[i][3] = fmaf(pv[i].w, vv[3].w, o[i][3]);
            }
        }
    }

    // Final normalize + store (lrow last written before the mid-tile barrier)
#pragma unroll
    for (int i = 0; i < 4; i++) {
        float inv = 1.0f / lrow[r4 + i];
        float4 v;
        v.x = o[i][0] * inv; v.y = o[i][1] * inv;
        v.z = o[i][2] * inv; v.w = o[i][3] * inv;
        *reinterpret_cast<float4*>(
            Og + hbase + (size_t)(q0 + r4 + i) * D_ + c4) = v;
    }
}

// ---------------------------------------------------------------------------
// Launch: 3 projection GEMMs -> flash attention v2 -> output GEMM (+bias)
// ---------------------------------------------------------------------------
extern "C" void kernel_launch(void* const* d_in, const int* in_sizes, int n_in,
                              void* d_out, int out_size) {
    const float* query = (const float*)d_in[0];
    const float* key   = (const float*)d_in[1];
    const float* value = (const float*)d_in[2];
    const float* Wq    = (const float*)d_in[3];
    const float* Wk    = (const float*)d_in[4];
    const float* Wv    = (const float*)d_in[5];
    const float* Wo    = (const float*)d_in[6];
    const float* bo    = (const float*)d_in[7];
    float* out = (float*)d_out;

    float *q, *k, *v, *a;
    cudaGetSymbolAddress((void**)&q, g_Q);
    cudaGetSymbolAddress((void**)&k, g_K);
    cudaGetSymbolAddress((void**)&v, g_V);
    cudaGetSymbolAddress((void**)&a, g_A);

    cudaFuncSetAttribute(flash_attn2,
                         cudaFuncAttributeMaxDynamicSharedMemorySize, FA_SMEM);

    dim3 gg(D_ / 128, M_ / 128);   // (8, 64)
    sgemm128<<<gg, 256>>>(query, Wq, nullptr, q);
    sgemm128<<<gg, 256>>>(key,   Wk, nullptr, k);
    sgemm128<<<gg, 256>>>(value, Wv, nullptr, v);
    flash_attn2<<<dim3(S_ / 64, B_ * H_), 256, FA_SMEM>>>(q, k, v, a);
    sgemm128<<<gg, 256>>>(a, Wo, bo, out);
}

// round 4
// speedup vs baseline: 1.4658x; 1.4658x over previous
#include <cuda_runtime.h>
#include <math.h>

// Problem constants
constexpr int B_  = 4;
constexpr int S_  = 2048;
constexpr int D_  = 1024;
constexpr int H_  = 16;
constexpr int HD_ = 64;
constexpr int M_  = B_ * S_;   // 8192

using u64 = unsigned long long;

// Packed fp32 helpers (Blackwell FFMA2 path, PTX-only)
__device__ __forceinline__ void fma2(u64& d, u64 a, u64 b) {
    asm("fma.rn.f32x2 %0, %1, %2, %0;" : "+l"(d) : "l"(a), "l"(b));
}
__device__ __forceinline__ u64 mul2(u64 a, u64 b) {
    u64 d; asm("mul.rn.f32x2 %0, %1, %2;" : "=l"(d) : "l"(a), "l"(b)); return d;
}
__device__ __forceinline__ u64 bcast2(float x) {
    u64 r; asm("mov.b64 %0, {%1, %1};" : "=l"(r) : "f"(x)); return r;
}
__device__ __forceinline__ void unpack2(float& lo, float& hi, u64 v) {
    asm("mov.b64 {%0, %1}, %2;" : "=f"(lo), "=f"(hi) : "l"(v));
}

// Scratch (static device arrays — allocation-free per harness rules)
__device__ float g_Q[(size_t)M_ * D_];
__device__ float g_K[(size_t)M_ * D_];
__device__ float g_V[(size_t)M_ * D_];
__device__ float g_A[(size_t)M_ * D_];

// ---------------------------------------------------------------------------
// SGEMM: C[M,1024] = A[M,1024] @ W[1024,1024] (+ bias)
// 128x128 tile, BK=16, 256 threads. Microtile = rows {4ty..+3, 64+4ty..+3} x
// cols {4tx..+3, 64+4tx..+3} (split halves -> Bs reads conflict-free).
// Math in fma.rn.f32x2 (packed over column pairs).
// ---------------------------------------------------------------------------
__global__ __launch_bounds__(256, 2)
void sgemm128(const float* __restrict__ A, const float* __restrict__ W,
              const float* __restrict__ bias, float* __restrict__ C) {
    constexpr int Kd = 1024, Nd = 1024;
    __shared__ float As[16][132];   // transposed A tile: As[k][m], pitch 132
    __shared__ float Bs[16][128];   // Bs[k][n]

    const int tid = threadIdx.x;
    const int tx = tid & 15, ty = tid >> 4;
    const int row0 = blockIdx.y * 128;
    const int col0 = blockIdx.x * 128;

    u64 acc2[8][4];
#pragma unroll
    for (int i = 0; i < 8; i++)
#pragma unroll
        for (int j = 0; j < 4; j++) acc2[i][j] = 0ull;

    const int arow = tid >> 2;          // 0..63
    const int acol = (tid & 3) << 2;    // 0,4,8,12
    const int brow = tid >> 5;          // 0..7
    const int bcol = (tid & 31) << 2;   // 0..124

    for (int k0 = 0; k0 < Kd; k0 += 16) {
#pragma unroll
        for (int u = 0; u < 2; u++) {
            int r = arow + u * 64;
            float4 v = *reinterpret_cast<const float4*>(
                A + (size_t)(row0 + r) * Kd + k0 + acol);
            As[acol + 0][r] = v.x;
            As[acol + 1][r] = v.y;
            As[acol + 2][r] = v.z;
            As[acol + 3][r] = v.w;
        }
#pragma unroll
        for (int u = 0; u < 2; u++) {
            int r = brow + u * 8;
            *reinterpret_cast<float4*>(&Bs[r][bcol]) =
                *reinterpret_cast<const float4*>(
                    W + (size_t)(k0 + r) * Nd + col0 + bcol);
        }
        __syncthreads();

#pragma unroll
        for (int kk = 0; kk < 16; kk++) {
            float4 alo = *reinterpret_cast<float4*>(&As[kk][ty * 4]);
            float4 ahi = *reinterpret_cast<float4*>(&As[kk][64 + ty * 4]);
            ulonglong2 blo = *reinterpret_cast<ulonglong2*>(&Bs[kk][tx * 4]);
            ulonglong2 bhi = *reinterpret_cast<ulonglong2*>(&Bs[kk][64 + tx * 4]);
            u64 a2[8];
            a2[0] = bcast2(alo.x); a2[1] = bcast2(alo.y);
            a2[2] = bcast2(alo.z); a2[3] = bcast2(alo.w);
            a2[4] = bcast2(ahi.x); a2[5] = bcast2(ahi.y);
            a2[6] = bcast2(ahi.z); a2[7] = bcast2(ahi.w);
#pragma unroll
            for (int i = 0; i < 8; i++) {
                fma2(acc2[i][0], a2[i], blo.x);
                fma2(acc2[i][1], a2[i], blo.y);
                fma2(acc2[i][2], a2[i], bhi.x);
                fma2(acc2[i][3], a2[i], bhi.y);
            }
        }
        __syncthreads();
    }

    // Epilogue: rows {4ty+i, 64+4ty+i}, cols {4tx.., 64+4tx..}
#pragma unroll
    for (int i = 0; i < 8; i++) {
        int r = row0 + ((i < 4) ? (ty * 4 + i) : (64 + ty * 4 + i - 4));
#pragma unroll
        for (int half = 0; half < 2; half++) {
            int c = col0 + half * 64 + tx * 4;
            float4 v;
            unpack2(v.x, v.y, acc2[i][half * 2 + 0]);
            unpack2(v.z, v.w, acc2[i][half * 2 + 1]);
            if (bias) {
                v.x += bias[c];     v.y += bias[c + 1];
                v.z += bias[c + 2]; v.w += bias[c + 3];
            }
            *reinterpret_cast<float4*>(C + (size_t)r * Nd + c) = v;
        }
    }
}

// ---------------------------------------------------------------------------
// Flash attention v3, fp32 + f32x2.
// Block = 64 query rows of one (b,h); key tile 64; 256 threads (16x16),
// 4x4 microtiles. Q/K/V tiles pitch exactly 64 with XOR swizzle
// g_phys = g ^ ((r>>2)&7) (float4 group granularity) -> all LDS.128
// conflict-free or broadcast. P tile pitch 64 linear.
// ---------------------------------------------------------------------------
constexpr int FA_SMEM = (4 * 64 * 64 + 128) * (int)sizeof(float);

__device__ __forceinline__ int sw64(int r, int g) {
    return r * 64 + (((g) ^ ((r >> 2) & 7)) << 2);
}

__global__ __launch_bounds__(256)
void flash_attn3(const float* __restrict__ Qg, const float* __restrict__ Kg,
                 const float* __restrict__ Vg, float* __restrict__ Og) {
    extern __shared__ float smf[];
    float* Qs = smf;                 // 64x64 swizzled
    float* Ks = Qs + 64 * 64;
    float* Vs = Ks + 64 * 64;
    float* Ps = Vs + 64 * 64;        // 64x64 linear
    float* mrow = Ps + 64 * 64;      // 64
    float* lrow = mrow + 64;         // 64

    const int tid = threadIdx.x;
    const int tx = tid & 15, ty = tid >> 4;
    const int b = blockIdx.y >> 4;   // H_ = 16
    const int h = blockIdx.y & 15;
    const int q0 = blockIdx.x * 64;
    const size_t hbase = (size_t)b * S_ * D_ + (size_t)h * HD_;

    // Load Q tile 64x64 (float4, swizzled store)
#pragma unroll
    for (int u = 0; u < 4; u++) {
        int idx = tid + u * 256;
        int r = idx >> 4;
        int g = idx & 15;
        float4 v = *reinterpret_cast<const float4*>(
            Qg + hbase + (size_t)(q0 + r) * D_ + g * 4);
        *reinterpret_cast<float4*>(&Qs[sw64(r, g)]) = v;
    }
    if (tid < 64) { mrow[tid] = -INFINITY; lrow[tid] = 0.f; }

    u64 o2[4][2];
#pragma unroll
    for (int i = 0; i < 4; i++) { o2[i][0] = 0ull; o2[i][1] = 0ull; }

    const int r4 = ty * 4;   // query-row group
    const int c4 = tx * 4;   // key-col / headdim-col group
    const float scale = 0.03125f;  // 1/sqrt(1024)

    for (int k0 = 0; k0 < S_; k0 += 64) {
        __syncthreads();
        // Load K,V tiles 64x64 (float4, swizzled store)
#pragma unroll
        for (int u = 0; u < 4; u++) {
            int idx = tid + u * 256;
            int r = idx >> 4;
            int g = idx & 15;
            float4 kv = *reinterpret_cast<const float4*>(
                Kg + hbase + (size_t)(k0 + r) * D_ + g * 4);
            float4 vv = *reinterpret_cast<const float4*>(
                Vg + hbase + (size_t)(k0 + r) * D_ + g * 4);
            *reinterpret_cast<float4*>(&Ks[sw64(r, g)]) = kv;
            *reinterpret_cast<float4*>(&Vs[sw64(r, g)]) = vv;
        }
        __syncthreads();

        // S = Q K^T : 4x4 per thread, packed over d
        u64 s2[4][4];
#pragma unroll
        for (int i = 0; i < 4; i++)
#pragma unroll
            for (int j = 0; j < 4; j++) s2[i][j] = 0ull;

#pragma unroll
        for (int g = 0; g < 16; g++) {
            ulonglong2 qa[4], kb[4];
#pragma unroll
            for (int i = 0; i < 4; i++)
                qa[i] = *reinterpret_cast<ulonglong2*>(&Qs[sw64(r4 + i, g)]);
#pragma unroll
            for (int j = 0; j < 4; j++)
                kb[j] = *reinterpret_cast<ulonglong2*>(&Ks[sw64(c4 + j, g)]);
#pragma unroll
            for (int i = 0; i < 4; i++)
#pragma unroll
                for (int j = 0; j < 4; j++) {
                    fma2(s2[i][j], qa[i].x, kb[j].x);
                    fma2(s2[i][j], qa[i].y, kb[j].y);
                }
        }

        // Horizontal add -> scalar scores
        float s[4][4];
#pragma unroll
        for (int i = 0; i < 4; i++)
#pragma unroll
            for (int j = 0; j < 4; j++) {
                float lo, hi; unpack2(lo, hi, s2[i][j]);
                s[i][j] = lo + hi;
            }

        // Online softmax: row owned by the 16 lanes sharing ty (half-warp)
        float cr[4];
#pragma unroll
        for (int i = 0; i < 4; i++) {
            float mx = fmaxf(fmaxf(s[i][0], s[i][1]), fmaxf(s[i][2], s[i][3]));
            mx *= scale;
#pragma unroll
            for (int off = 8; off >= 1; off >>= 1)
                mx = fmaxf(mx, __shfl_xor_sync(0xffffffffu, mx, off, 16));
            float m_old = mrow[r4 + i];
            float m_new = fmaxf(m_old, mx);
            cr[i] = __expf(m_old - m_new);
            float e0 = __expf(fmaf(s[i][0], scale, -m_new));
            float e1 = __expf(fmaf(s[i][1], scale, -m_new));
            float e2 = __expf(fmaf(s[i][2], scale, -m_new));
            float e3 = __expf(fmaf(s[i][3], scale, -m_new));
            float rs = (e0 + e1) + (e2 + e3);
#pragma unroll
            for (int off = 8; off >= 1; off >>= 1)
                rs += __shfl_xor_sync(0xffffffffu, rs, off, 16);
            if (tx == 0) {
                mrow[r4 + i] = m_new;
                lrow[r4 + i] = lrow[r4 + i] * cr[i] + rs;
            }
            float4 e; e.x = e0; e.y = e1; e.z = e2; e.w = e3;
            *reinterpret_cast<float4*>(&Ps[(r4 + i) * 64 + c4]) = e;
            // rescale running output (packed)
            u64 cr2 = bcast2(cr[i]);
            o2[i][0] = mul2(o2[i][0], cr2);
            o2[i][1] = mul2(o2[i][1], cr2);
        }
        __syncthreads();

        // O += P @ V : packed over headdim-column pairs
#pragma unroll
        for (int k = 0; k < 64; k += 4) {
            float4 pv[4];
            ulonglong2 vv[4];
#pragma unroll
            for (int i = 0; i < 4; i++)
                pv[i] = *reinterpret_cast<float4*>(&Ps[(r4 + i) * 64 + k]);
#pragma unroll
            for (int t = 0; t < 4; t++)
                vv[t] = *reinterpret_cast<ulonglong2*>(&Vs[sw64(k + t, tx)]);
#pragma unroll
            for (int t = 0; t < 4; t++) {
#pragma unroll
                for (int i = 0; i < 4; i++) {
                    float p = (t == 0) ? pv[i].x : (t == 1) ? pv[i].y
                            : (t == 2) ? pv[i].z : pv[i].w;
                    u64 pp = bcast2(p);
                    fma2(o2[i][0], pp, vv[t].x);
                    fma2(o2[i][1], pp, vv[t].y);
                }
            }
        }
    }

    // Final normalize + store
#pragma unroll
    for (int i = 0; i < 4; i++) {
        float inv = 1.0f / lrow[r4 + i];
        float4 v;
        unpack2(v.x, v.y, o2[i][0]);
        unpack2(v.z, v.w, o2[i][1]);
        v.x *= inv; v.y *= inv; v.z *= inv; v.w *= inv;
        *reinterpret_cast<float4*>(
            Og + hbase + (size_t)(q0 + r4 + i) * D_ + c4) = v;
    }
}

// ---------------------------------------------------------------------------
// Launch: 3 projection GEMMs -> flash attention v3 -> output GEMM (+bias)
// ---------------------------------------------------------------------------
extern "C" void kernel_launch(void* const* d_in, const int* in_sizes, int n_in,
                              void* d_out, int out_size) {
    const float* query = (const float*)d_in[0];
    const float* key   = (const float*)d_in[1];
    const float* value = (const float*)d_in[2];
    const float* Wq    = (const float*)d_in[3];
    const float* Wk    = (const float*)d_in[4];
    const float* Wv    = (const float*)d_in[5];
    const float* Wo    = (const float*)d_in[6];
    const float* bo    = (const float*)d_in[7];
    float* out = (float*)d_out;

    float *q, *k, *v, *a;
    cudaGetSymbolAddress((void**)&q, g_Q);
    cudaGetSymbolAddress((void**)&k, g_K);
    cudaGetSymbolAddress((void**)&v, g_V);
    cudaGetSymbolAddress((void**)&a, g_A);

    cudaFuncSetAttribute(flash_attn3,
                         cudaFuncAttributeMaxDynamicSharedMemorySize, FA_SMEM);

    dim3 gg(D_ / 128, M_ / 128);   // (8, 64)
    sgemm128<<<gg, 256>>>(query, Wq, nullptr, q);
    sgemm128<<<gg, 256>>>(key,   Wk, nullptr, k);
    sgemm128<<<gg, 256>>>(value, Wv, nullptr, v);
    flash_attn3<<<dim3(S_ / 64, B_ * H_), 256, FA_SMEM>>>(q, k, v, a);
    sgemm128<<<gg, 256>>>(a, Wo, bo, out);
}

// round 7
// speedup vs baseline: 1.8474x; 1.2604x over previous
#include <cuda_runtime.h>
#include <cuda_bf16.h>
#include <math.h>
#include <stdint.h>

// Problem constants
constexpr int B_  = 4;
constexpr int S_  = 2048;
constexpr int D_  = 1024;
constexpr int H_  = 16;
constexpr int HD_ = 64;
constexpr int M_  = B_ * S_;   // 8192

using u64 = unsigned long long;

// ---------------- packed fp32 helpers (FFMA2) ----------------
__device__ __forceinline__ void fma2(u64& d, u64 a, u64 b) {
    asm("fma.rn.f32x2 %0, %1, %2, %0;" : "+l"(d) : "l"(a), "l"(b));
}
__device__ __forceinline__ u64 mul2(u64 a, u64 b) {
    u64 d; asm("mul.rn.f32x2 %0, %1, %2;" : "=l"(d) : "l"(a), "l"(b)); return d;
}
__device__ __forceinline__ u64 bcast2(float x) {
    u64 r; asm("mov.b64 %0, {%1, %1};" : "=l"(r) : "f"(x)); return r;
}
__device__ __forceinline__ void unpack2(float& lo, float& hi, u64 v) {
    asm("mov.b64 {%0, %1}, %2;" : "=f"(lo), "=f"(hi) : "l"(v));
}

// ---------------- mma.sync / ldmatrix / cp.async helpers (sm_80 baseline) ---
__device__ __forceinline__ uint32_t smem_u32(const void* p) {
    uint32_t a;
    asm("{ .reg .u64 t; cvta.to.shared.u64 t, %1; cvt.u32.u64 %0, t; }"
        : "=r"(a) : "l"(p));
    return a;
}
__device__ __forceinline__ void ldsm_x4(uint32_t& r0, uint32_t& r1,
                                        uint32_t& r2, uint32_t& r3, uint32_t a) {
    asm volatile("ldmatrix.sync.aligned.m8n8.x4.shared.b16 {%0,%1,%2,%3}, [%4];"
                 : "=r"(r0), "=r"(r1), "=r"(r2), "=r"(r3) : "r"(a));
}
__device__ __forceinline__ void mma_bf16(float* d, const uint32_t* a,
                                         uint32_t b0, uint32_t b1) {
    asm volatile(
        "mma.sync.aligned.m16n8k16.row.col.f32.bf16.bf16.f32 "
        "{%0,%1,%2,%3}, {%4,%5,%6,%7}, {%8,%9}, {%0,%1,%2,%3};"
        : "+f"(d[0]), "+f"(d[1]), "+f"(d[2]), "+f"(d[3])
        : "r"(a[0]), "r"(a[1]), "r"(a[2]), "r"(a[3]), "r"(b0), "r"(b1));
}
__device__ __forceinline__ void cp16(uint32_t dst, const void* src) {
    asm volatile("cp.async.cg.shared.global [%0], [%1], 16;"
                 :: "r"(dst), "l"(src));
}
#define CP_COMMIT() asm volatile("cp.async.commit_group;" ::: "memory")
#define CP_WAIT1()  asm volatile("cp.async.wait_group 1;" ::: "memory")
#define CP_WAIT0()  asm volatile("cp.async.wait_group 0;" ::: "memory")

__device__ __forceinline__ uint32_t sw128(uint32_t off) {
    return off ^ ((off >> 3) & 0x70);
}

// ---------------- scratch ----------------
__device__ float g_Q[(size_t)M_ * D_];
__device__ float g_K[(size_t)M_ * D_];
__device__ float g_V[(size_t)M_ * D_];
__device__ float g_A[(size_t)M_ * D_];
__device__ __nv_bfloat16 g_hi[(size_t)M_ * D_];
__device__ __nv_bfloat16 g_lo[(size_t)M_ * D_];
// transposed weight splits: [w][hi=0/lo=1][N][K]
__device__ __nv_bfloat16 g_Wt[4][2][(size_t)D_ * D_];

// ---------------------------------------------------------------------------
// split: fp32 -> (hi, lo) bf16. 8 elements per thread, vectorized I/O.
// ---------------------------------------------------------------------------
__global__ __launch_bounds__(256)
void split_bf16(const float4* __restrict__ x, uint4* __restrict__ hi,
                uint4* __restrict__ lo) {
    size_t i = (size_t)blockIdx.x * blockDim.x + threadIdx.x;
    float4 a = x[2 * i], b = x[2 * i + 1];
    float v[8] = {a.x, a.y, a.z, a.w, b.x, b.y, b.z, b.w};
    unsigned short hs[8], ls[8];
#pragma unroll
    for (int j = 0; j < 8; j++) {
        __nv_bfloat16 h = __float2bfloat16_rn(v[j]);
        __nv_bfloat16 l = __float2bfloat16_rn(v[j] - __bfloat162float(h));
        hs[j] = *reinterpret_cast<unsigned short*>(&h);
        ls[j] = *reinterpret_cast<unsigned short*>(&l);
    }
    hi[i] = *reinterpret_cast<uint4*>(hs);
    lo[i] = *reinterpret_cast<uint4*>(ls);
}

// ---------------------------------------------------------------------------
// transpose + split: W[K][N] fp32 -> Wt_hi/lo[N][K] bf16 (32x32 smem tile)
// ---------------------------------------------------------------------------
__global__ __launch_bounds__(256)
void transpose_split(const float* __restrict__ W, __nv_bfloat16* __restrict__ Th,
                     __nv_bfloat16* __restrict__ Tl) {
    __shared__ float t[32][33];
    const int tx = threadIdx.x, ty = threadIdx.y;
    const int bx = blockIdx.x, by = blockIdx.y;
#pragma unroll
    for (int j = 0; j < 32; j += 8)
        t[ty + j][tx] = W[(size_t)(bx * 32 + ty + j) * D_ + by * 32 + tx];
    __syncthreads();
#pragma unroll
    for (int j = 0; j < 32; j += 8) {
        float v = t[tx][ty + j];
        __nv_bfloat16 h = __float2bfloat16_rn(v);
        __nv_bfloat16 l = __float2bfloat16_rn(v - __bfloat162float(h));
        size_t o = (size_t)(by * 32 + ty + j) * D_ + bx * 32 + tx;
        Th[o] = h;
        Tl[o] = l;
    }
}

// ---------------------------------------------------------------------------
// Tensor-core GEMM via mma.sync (bf16 split precision):
// C[M,1024] = A @ W (+bias), fp32 accumulate in registers.
// A as (Ahi, Alo) bf16 [M][K]; W transposed as (Bhi, Blo) bf16 [N][K].
// 3 K=1024 passes: hi*Bhi + hi*Blo + lo*Bhi.
// CTA tile 128x128, 8 warps of 64x32, k-block 64, cp.async double buffer,
// SW128-swizzled smem, ldmatrix fragment loads.
// ---------------------------------------------------------------------------
constexpr int GEMM_SMEM = 4 * 16384;   // A0,B0,A1,B1 (128x64 bf16 each)

__global__ __launch_bounds__(256)
void gemm_mma(const __nv_bfloat16* __restrict__ Ahi,
              const __nv_bfloat16* __restrict__ Alo,
              const __nv_bfloat16* __restrict__ Bhi,
              const __nv_bfloat16* __restrict__ Blo,
              const float* __restrict__ bias,
              float* __restrict__ C) {
    extern __shared__ char smem[];
    const uint32_t sm_base = smem_u32(smem);
    const int tid = threadIdx.x;
    const int wid = tid >> 5, lane = tid & 31;
    const int wm = wid & 1;        // m-warp: 0/1 -> m offset 0/64
    const int wn = wid >> 1;       // n-warp: 0..3 -> n offset 0/32/64/96
    const int col0 = blockIdx.x * 128;
    const int row0 = blockIdx.y * 128;

    const int AOFF[2] = {0, 32768};
    const int BOFF[2] = {16384, 49152};

    float acc[4][4][4];
#pragma unroll
    for (int i = 0; i < 4; i++)
#pragma unroll
        for (int j = 0; j < 4; j++)
#pragma unroll
            for (int q = 0; q < 4; q++) acc[i][j][q] = 0.f;

    // per-thread cp.async slots: 4 chunks/tile, r = id>>3, c = id&7
    const int ld_r = tid >> 3;       // base row for u=0 (rows step by 32)
    const int ld_c = tid & 7;        // 16B chunk in 128B row

    auto issue_tile = [&](int buf, const __nv_bfloat16* As,
                          const __nv_bfloat16* Bs, int k0) {
#pragma unroll
        for (int u = 0; u < 4; u++) {
            int r = ld_r + u * 32;
            uint32_t off = sw128((uint32_t)(r * 128 + ld_c * 16));
            cp16(sm_base + AOFF[buf] + off,
                 As + (size_t)(row0 + r) * 1024 + k0 + ld_c * 8);
            cp16(sm_base + BOFF[buf] + off,
                 Bs + (size_t)(col0 + r) * 1024 + k0 + ld_c * 8);
        }
        CP_COMMIT();
    };

    // ldmatrix lane-address components (within 128x64bf16 = 128B-row tile)
    const int a_row_l = (lane & 7) + ((lane >> 3) & 1) * 8;
    const int a_kb_l  = ((lane >> 4) & 1) * 16;
    const int b_row_l = (lane & 7) + ((lane >> 4) & 1) * 8;
    const int b_kb_l  = ((lane >> 3) & 1) * 16;

    constexpr int NBLK = 48;   // 3 passes x 16 k-blocks of 64
    issue_tile(0, Ahi, Bhi, 0);

    for (int i = 0; i < NBLK; i++) {
        if (i + 1 < NBLK) {
            int j = i + 1;
            int pass = j >> 4;
            int k0 = (j & 15) << 6;
            issue_tile(j & 1, (pass == 2) ? Alo : Ahi,
                       (pass == 1) ? Blo : Bhi, k0);
            CP_WAIT1();
        } else {
            CP_WAIT0();
        }
        __syncthreads();

        const uint32_t a_base = sm_base + AOFF[i & 1];
        const uint32_t b_base = sm_base + BOFF[i & 1];
#pragma unroll
        for (int kk = 0; kk < 4; kk++) {
            uint32_t af[4][4];
#pragma unroll
            for (int mt = 0; mt < 4; mt++) {
                int row = wm * 64 + mt * 16 + a_row_l;
                uint32_t addr = a_base + sw128((uint32_t)(row * 128 + kk * 32 + a_kb_l));
                ldsm_x4(af[mt][0], af[mt][1], af[mt][2], af[mt][3], addr);
            }
            uint32_t bf[2][4];
#pragma unroll
            for (int nt2 = 0; nt2 < 2; nt2++) {
                int row = wn * 32 + nt2 * 16 + b_row_l;
                uint32_t addr = b_base + sw128((uint32_t)(row * 128 + kk * 32 + b_kb_l));
                ldsm_x4(bf[nt2][0], bf[nt2][1], bf[nt2][2], bf[nt2][3], addr);
            }
#pragma unroll
            for (int mt = 0; mt < 4; mt++)
#pragma unroll
                for (int nt = 0; nt < 4; nt++)
                    mma_bf16(acc[mt][nt], af[mt],
                             bf[nt >> 1][(nt & 1) * 2],
                             bf[nt >> 1][(nt & 1) * 2 + 1]);
        }
        __syncthreads();
    }

    // Epilogue: fp32 register accumulators -> C (+bias), float2 stores
#pragma unroll
    for (int mt = 0; mt < 4; mt++) {
#pragma unroll
        for (int nt = 0; nt < 4; nt++) {
            int r = row0 + wm * 64 + mt * 16 + (lane >> 2);
            int c = col0 + wn * 32 + nt * 8 + (lane & 3) * 2;
            float b0 = 0.f, b1 = 0.f;
            if (bias) { b0 = bias[c]; b1 = bias[c + 1]; }
            float2 v0 = {acc[mt][nt][0] + b0, acc[mt][nt][1] + b1};
            float2 v1 = {acc[mt][nt][2] + b0, acc[mt][nt][3] + b1};
            *reinterpret_cast<float2*>(C + (size_t)r * 1024 + c) = v0;
            *reinterpret_cast<float2*>(C + (size_t)(r + 8) * 1024 + c) = v1;
        }
    }
}

// ---------------------------------------------------------------------------
// Flash attention v3 (unchanged from R3): fp32 + f32x2, XOR-swizzled smem.
// ---------------------------------------------------------------------------
constexpr int FA_SMEM = (4 * 64 * 64 + 128) * (int)sizeof(float);

__device__ __forceinline__ int sw64(int r, int g) {
    return r * 64 + (((g) ^ ((r >> 2) & 7)) << 2);
}

__global__ __launch_bounds__(256)
void flash_attn3(const float* __restrict__ Qg, const float* __restrict__ Kg,
                 const float* __restrict__ Vg, float* __restrict__ Og) {
    extern __shared__ float smf[];
    float* Qs = smf;
    float* Ks = Qs + 64 * 64;
    float* Vs = Ks + 64 * 64;
    float* Ps = Vs + 64 * 64;
    float* mrow = Ps + 64 * 64;
    float* lrow = mrow + 64;

    const int tid = threadIdx.x;
    const int tx = tid & 15, ty = tid >> 4;
    const int b = blockIdx.y >> 4;
    const int h = blockIdx.y & 15;
    const int q0 = blockIdx.x * 64;
    const size_t hbase = (size_t)b * S_ * D_ + (size_t)h * HD_;

#pragma unroll
    for (int u = 0; u < 4; u++) {
        int idx = tid + u * 256;
        int r = idx >> 4;
        int g = idx & 15;
        float4 v = *reinterpret_cast<const float4*>(
            Qg + hbase + (size_t)(q0 + r) * D_ + g * 4);
        *reinterpret_cast<float4*>(&Qs[sw64(r, g)]) = v;
    }
    if (tid < 64) { mrow[tid] = -INFINITY; lrow[tid] = 0.f; }

    u64 o2[4][2];
#pragma unroll
    for (int i = 0; i < 4; i++) { o2[i][0] = 0ull; o2[i][1] = 0ull; }

    const int r4 = ty * 4;
    const int c4 = tx * 4;
    const float scale = 0.03125f;

    for (int k0 = 0; k0 < S_; k0 += 64) {
        __syncthreads();
#pragma unroll
        for (int u = 0; u < 4; u++) {
            int idx = tid + u * 256;
            int r = idx >> 4;
            int g = idx & 15;
            float4 kv = *reinterpret_cast<const float4*>(
                Kg + hbase + (size_t)(k0 + r) * D_ + g * 4);
            float4 vv = *reinterpret_cast<const float4*>(
                Vg + hbase + (size_t)(k0 + r) * D_ + g * 4);
            *reinterpret_cast<float4*>(&Ks[sw64(r, g)]) = kv;
            *reinterpret_cast<float4*>(&Vs[sw64(r, g)]) = vv;
        }
        __syncthreads();

        u64 s2[4][4];
#pragma unroll
        for (int i = 0; i < 4; i++)
#pragma unroll
            for (int j = 0; j < 4; j++) s2[i][j] = 0ull;

#pragma unroll
        for (int g = 0; g < 16; g++) {
            ulonglong2 qa[4], kb[4];
#pragma unroll
            for (int i = 0; i < 4; i++)
                qa[i] = *reinterpret_cast<ulonglong2*>(&Qs[sw64(r4 + i, g)]);
#pragma unroll
            for (int j = 0; j < 4; j++)
                kb[j] = *reinterpret_cast<ulonglong2*>(&Ks[sw64(c4 + j, g)]);
#pragma unroll
            for (int i = 0; i < 4; i++)
#pragma unroll
                for (int j = 0; j < 4; j++) {
                    fma2(s2[i][j], qa[i].x, kb[j].x);
                    fma2(s2[i][j], qa[i].y, kb[j].y);
                }
        }

        float s[4][4];
#pragma unroll
        for (int i = 0; i < 4; i++)
#pragma unroll
            for (int j = 0; j < 4; j++) {
                float lo, hi; unpack2(lo, hi, s2[i][j]);
                s[i][j] = lo + hi;
            }

        float cr[4];
#pragma unroll
        for (int i = 0; i < 4; i++) {
            float mx = fmaxf(fmaxf(s[i][0], s[i][1]), fmaxf(s[i][2], s[i][3]));
            mx *= scale;
#pragma unroll
            for (int off = 8; off >= 1; off >>= 1)
                mx = fmaxf(mx, __shfl_xor_sync(0xffffffffu, mx, off, 16));
            float m_old = mrow[r4 + i];
            float m_new = fmaxf(m_old, mx);
            cr[i] = __expf(m_old - m_new);
            float e0 = __expf(fmaf(s[i][0], scale, -m_new));
            float e1 = __expf(fmaf(s[i][1], scale, -m_new));
            float e2 = __expf(fmaf(s[i][2], scale, -m_new));
            float e3 = __expf(fmaf(s[i][3], scale, -m_new));
            float rs = (e0 + e1) + (e2 + e3);
#pragma unroll
            for (int off = 8; off >= 1; off >>= 1)
                rs += __shfl_xor_sync(0xffffffffu, rs, off, 16);
            if (tx == 0) {
                mrow[r4 + i] = m_new;
                lrow[r4 + i] = lrow[r4 + i] * cr[i] + rs;
            }
            float4 e; e.x = e0; e.y = e1; e.z = e2; e.w = e3;
            *reinterpret_cast<float4*>(&Ps[(r4 + i) * 64 + c4]) = e;
            u64 cr2 = bcast2(cr[i]);
            o2[i][0] = mul2(o2[i][0], cr2);
            o2[i][1] = mul2(o2[i][1], cr2);
        }
        __syncthreads();

#pragma unroll
        for (int k = 0; k < 64; k += 4) {
            float4 pv[4];
            ulonglong2 vv[4];
#pragma unroll
            for (int i = 0; i < 4; i++)
                pv[i] = *reinterpret_cast<float4*>(&Ps[(r4 + i) * 64 + k]);
#pragma unroll
            for (int t = 0; t < 4; t++)
                vv[t] = *reinterpret_cast<ulonglong2*>(&Vs[sw64(k + t, tx)]);
#pragma unroll
            for (int t = 0; t < 4; t++) {
#pragma unroll
                for (int i = 0; i < 4; i++) {
                    float p = (t == 0) ? pv[i].x : (t == 1) ? pv[i].y
                            : (t == 2) ? pv[i].z : pv[i].w;
                    u64 pp = bcast2(p);
                    fma2(o2[i][0], pp, vv[t].x);
                    fma2(o2[i][1], pp, vv[t].y);
                }
            }
        }
    }

#pragma unroll
    for (int i = 0; i < 4; i++) {
        float inv = 1.0f / lrow[r4 + i];
        float4 v;
        unpack2(v.x, v.y, o2[i][0]);
        unpack2(v.z, v.w, o2[i][1]);
        v.x *= inv; v.y *= inv; v.z *= inv; v.w *= inv;
        *reinterpret_cast<float4*>(
            Og + hbase + (size_t)(q0 + r4 + i) * D_ + c4) = v;
    }
}

// ---------------------------------------------------------------------------
// Launch
// ---------------------------------------------------------------------------
extern "C" void kernel_launch(void* const* d_in, const int* in_sizes, int n_in,
                              void* d_out, int out_size) {
    const float* query = (const float*)d_in[0];
    const float* key   = (const float*)d_in[1];
    const float* value = (const float*)d_in[2];
    const float* Wq    = (const float*)d_in[3];
    const float* Wk    = (const float*)d_in[4];
    const float* Wv    = (const float*)d_in[5];
    const float* Wo    = (const float*)d_in[6];
    const float* bo    = (const float*)d_in[7];
    float* out = (float*)d_out;

    float *q, *k, *v, *a;
    cudaGetSymbolAddress((void**)&q, g_Q);
    cudaGetSymbolAddress((void**)&k, g_K);
    cudaGetSymbolAddress((void**)&v, g_V);
    cudaGetSymbolAddress((void**)&a, g_A);
    __nv_bfloat16 *hi, *lo, *wt;
    cudaGetSymbolAddress((void**)&hi, g_hi);
    cudaGetSymbolAddress((void**)&lo, g_lo);
    cudaGetSymbolAddress((void**)&wt, g_Wt);
    const size_t WSZ = (size_t)D_ * D_;
    auto wth = [&](int w) { return wt + (size_t)w * 2 * WSZ; };
    auto wtl = [&](int w) { return wt + (size_t)w * 2 * WSZ + WSZ; };

    cudaFuncSetAttribute(flash_attn3,
                         cudaFuncAttributeMaxDynamicSharedMemorySize, FA_SMEM);
    cudaFuncSetAttribute(gemm_mma,
                         cudaFuncAttributeMaxDynamicSharedMemorySize, GEMM_SMEM);

    // Transpose+split all four weight matrices
    dim3 tg(32, 32), tb(32, 8);
    transpose_split<<<tg, tb>>>(Wq, wth(0), wtl(0));
    transpose_split<<<tg, tb>>>(Wk, wth(1), wtl(1));
    transpose_split<<<tg, tb>>>(Wv, wth(2), wtl(2));
    transpose_split<<<tg, tb>>>(Wo, wth(3), wtl(3));

    dim3 gg(D_ / 128, M_ / 128);   // (8, 64)
    const int SPLIT_GRID = (int)((size_t)M_ * D_ / (8 * 256));

    split_bf16<<<SPLIT_GRID, 256>>>((const float4*)query, (uint4*)hi, (uint4*)lo);
    gemm_mma<<<gg, 256, GEMM_SMEM>>>(hi, lo, wth(0), wtl(0), nullptr, q);
    split_bf16<<<SPLIT_GRID, 256>>>((const float4*)key, (uint4*)hi, (uint4*)lo);
    gemm_mma<<<gg, 256, GEMM_SMEM>>>(hi, lo, wth(1), wtl(1), nullptr, k);
    split_bf16<<<SPLIT_GRID, 256>>>((const float4*)value, (uint4*)hi, (uint4*)lo);
    gemm_mma<<<gg, 256, GEMM_SMEM>>>(hi, lo, wth(2), wtl(2), nullptr, v);

    flash_attn3<<<dim3(S_ / 64, B_ * H_), 256, FA_SMEM>>>(q, k, v, a);

    split_bf16<<<SPLIT_GRID, 256>>>((const float4*)a, (uint4*)hi, (uint4*)lo);
    gemm_mma<<<gg, 256, GEMM_SMEM>>>(hi, lo, wth(3), wtl(3), bo, out);
}